// round 5
// baseline (speedup 1.0000x reference)
#include <cuda_runtime.h>
#include <math.h>

#define B_DIM 2048
#define T_DIM 256
#define IN_DIM 128
#define H_DIM 256
#define G3 768   // 3*H

// Scratch (static device arrays: the sanctioned no-alloc workaround)
__device__ float g_gi[(size_t)B_DIM * T_DIM * G3];  // [B*T, 768]
__device__ float g_gh[(size_t)B_DIM * G3];          // [B, 768]
__device__ float g_h [(size_t)B_DIM * H_DIM];       // [B, 256]  hidden (exactly -1/0/+1)

// ---------------------------------------------------------------------------
// XLA f32 tanh: Eigen rational poly, clamp +-7.90531110763549805,
// |x| < 0.0004 -> x.  Poly steps CONTRACTED to single-rounding FMA
// (matches XLA:CPU emission where LLVM contracts add(mul) -> vfmadd).
// ---------------------------------------------------------------------------
__device__ __forceinline__ float tanh_xla(float x) {
    const float kClamp = 7.90531110763549805f;
    float xc = fminf(fmaxf(x, -kClamp), kClamp);

    const float a1  = 4.89352455891786e-03f;
    const float a3  = 6.37261928875436e-04f;
    const float a5  = 1.48572235717979e-05f;
    const float a7  = 5.12229709037114e-08f;
    const float a9  = -8.60467152213735e-11f;
    const float a11 = 2.00018790482477e-13f;
    const float a13 = -2.76076847742355e-16f;
    const float b0  = 4.89352518554385e-03f;
    const float b2  = 2.26843463243900e-03f;
    const float b4  = 1.18534705686654e-04f;
    const float b6  = 1.19825839466702e-06f;

    float x2 = __fmul_rn(xc, xc);

    float p = a13;
    p = fmaf(x2, p, a11);
    p = fmaf(x2, p, a9);
    p = fmaf(x2, p, a7);
    p = fmaf(x2, p, a5);
    p = fmaf(x2, p, a3);
    p = fmaf(x2, p, a1);
    float num = __fmul_rn(xc, p);

    float q = b6;
    q = fmaf(x2, q, b4);
    q = fmaf(x2, q, b2);
    q = fmaf(x2, q, b0);

    float ratio = __fdiv_rn(num, q);
    return (fabsf(x) < 0.0004f) ? x : ratio;
}

// XLA logistic expander: 0.5 + 0.5 * tanh(0.5 * x), final add contracted.
__device__ __forceinline__ float sigmoid_xla(float x) {
    float t = tanh_xla(__fmul_rn(0.5f, x));
    return fmaf(0.5f, t, 0.5f);
}

// ---------------------------------------------------------------------------
// C[M,768] = A[M,K] * W[768,K]^T — each output is one serial ascending-k FMA
// chain from zero (bit-identical to Eigen gebp / cuBLAS SGEMM accumulation).
// Tiles: BM=64, BN=64, BK=16, 128 threads, per-thread 8x4.
// ---------------------------------------------------------------------------
template<int K>
__global__ __launch_bounds__(128) void sgemm_nt(
    const float* __restrict__ A, const float* __restrict__ W, float* __restrict__ C)
{
    __shared__ float As[16][65];
    __shared__ float Ws[16][65];

    const int tid = threadIdx.x;
    const int tm  = tid >> 4;
    const int tn  = tid & 15;
    const size_t m0 = (size_t)blockIdx.x * 64;
    const int    n0 = blockIdx.y * 64;

    const int lk = tid & 15;
    const int lm = tid >> 4;

    float acc[8][4];
#pragma unroll
    for (int i = 0; i < 8; i++)
#pragma unroll
        for (int j = 0; j < 4; j++) acc[i][j] = 0.0f;

#pragma unroll 1
    for (int k0 = 0; k0 < K; k0 += 16) {
#pragma unroll
        for (int it = 0; it < 8; it++) {
            int m = lm + it * 8;
            As[lk][m] = A[(m0 + m) * K + (k0 + lk)];
            Ws[lk][m] = W[(size_t)(n0 + m) * K + (k0 + lk)];
        }
        __syncthreads();
#pragma unroll
        for (int kk = 0; kk < 16; kk++) {
            float a[8], b[4];
#pragma unroll
            for (int i = 0; i < 8; i++) a[i] = As[kk][tm * 8 + i];
#pragma unroll
            for (int j = 0; j < 4; j++) b[j] = Ws[kk][tn * 4 + j];
#pragma unroll
            for (int i = 0; i < 8; i++)
#pragma unroll
                for (int j = 0; j < 4; j++)
                    acc[i][j] = fmaf(a[i], b[j], acc[i][j]);
        }
        __syncthreads();
    }

#pragma unroll
    for (int i = 0; i < 8; i++) {
        size_t row = m0 + tm * 8 + i;
#pragma unroll
        for (int j = 0; j < 4; j++)
            C[row * G3 + (n0 + tn * 4 + j)] = acc[i][j];
    }
}

// ---------------------------------------------------------------------------
// Pointwise GRU combine + sign. XLA expression order, contraction applied
// exactly where LLVM's DAG combiner fuses: fma(r,h_n,i_n) and
// fma(1-z, n, z*h) (operand-0 mul fused; z*h separately rounded).
// ---------------------------------------------------------------------------
__global__ __launch_bounds__(256) void gru_combine(
    const float* __restrict__ b_ih, const float* __restrict__ b_hh,
    int t, float* __restrict__ out, int is_last)
{
    int idx = blockIdx.x * blockDim.x + threadIdx.x;
    int b = idx >> 8;
    int h = idx & 255;

    const float* gi = &g_gi[((size_t)b * T_DIM + t) * G3];
    const float* gh = &g_gh[(size_t)b * G3];

    float i_r = __fadd_rn(gi[h],             b_ih[h]);
    float i_z = __fadd_rn(gi[h +     H_DIM], b_ih[h +     H_DIM]);
    float i_n = __fadd_rn(gi[h + 2 * H_DIM], b_ih[h + 2 * H_DIM]);
    float h_r = __fadd_rn(gh[h],             b_hh[h]);
    float h_z = __fadd_rn(gh[h +     H_DIM], b_hh[h +     H_DIM]);
    float h_n = __fadd_rn(gh[h + 2 * H_DIM], b_hh[h + 2 * H_DIM]);

    float r = sigmoid_xla(__fadd_rn(i_r, h_r));
    float z = sigmoid_xla(__fadd_rn(i_z, h_z));
    float n = tanh_xla(fmaf(r, h_n, i_n));

    float hprev = g_h[idx];
    float one_minus_z = __fsub_rn(1.0f, z);
    float zh   = __fmul_rn(z, hprev);
    float hnew = fmaf(one_minus_z, n, zh);

    float s = (hnew > 0.0f) ? 1.0f : ((hnew < 0.0f) ? -1.0f : 0.0f);

    g_h[idx] = s;
    if (is_last) out[idx] = s;
}

extern "C" void kernel_launch(void* const* d_in, const int* in_sizes, int n_in,
                              void* d_out, int out_size)
{
    const float* x   = (const float*)d_in[0];  // [2048, 256, 128]
    const float* Wih = (const float*)d_in[1];  // [768, 128]
    const float* Whh = (const float*)d_in[2];  // [768, 256]
    const float* bih = (const float*)d_in[3];  // [768]
    const float* bhh = (const float*)d_in[4];  // [768]
    float* out = (float*)d_out;                // [2048, 256]

    float *gi_p, *gh_p, *h_p;
    cudaGetSymbolAddress((void**)&gi_p, g_gi);
    cudaGetSymbolAddress((void**)&gh_p, g_gh);
    cudaGetSymbolAddress((void**)&h_p,  g_h);

    cudaMemsetAsync(h_p, 0, sizeof(float) * (size_t)B_DIM * H_DIM);

    // Phase 1: gi = X @ W_ih^T for all timesteps (M = B*T = 524288, K = 128).
    {
        dim3 grid((B_DIM * T_DIM) / 64, G3 / 64);
        sgemm_nt<IN_DIM><<<grid, 128>>>(x, Wih, gi_p);
    }

    // Phase 2: sequential recurrence.
    {
        dim3 grid_gh(B_DIM / 64, G3 / 64);
        int combine_blocks = (B_DIM * H_DIM) / 256;
        for (int t = 0; t < T_DIM; t++) {
            sgemm_nt<H_DIM><<<grid_gh, 128>>>(h_p, Whh, gh_p);
            gru_combine<<<combine_blocks, 256>>>(bih, bhh, t, out, (t == T_DIM - 1) ? 1 : 0);
        }
    }
}

// round 6
// speedup vs baseline: 1.0837x; 1.0837x over previous
#include <cuda_runtime.h>
#include <math.h>

#define B_DIM 2048
#define T_DIM 256
#define IN_DIM 128
#define H_DIM 256
#define G3 768   // 3*H

typedef unsigned long long ull;

// Scratch (static device arrays: the sanctioned no-alloc workaround)
__device__ float g_gi[(size_t)B_DIM * T_DIM * G3];  // [B*T, 768]
__device__ float g_h0[(size_t)B_DIM * H_DIM];       // hidden double-buffer A
__device__ float g_h1[(size_t)B_DIM * H_DIM];       // hidden double-buffer B

// ---------------------------------------------------------------------------
// Packed fp32x2 helpers (sm_100+). Each half is an independent IEEE fp32 FMA
// with single rounding -> bit-identical to scalar FFMA chains.
// ---------------------------------------------------------------------------
__device__ __forceinline__ ull dup2(float x) {
    ull r; asm("mov.b64 %0, {%1, %1};" : "=l"(r) : "f"(x)); return r;
}
__device__ __forceinline__ void ffma2(ull &d, ull a, ull b) {
    asm("fma.rn.f32x2 %0, %1, %2, %0;" : "+l"(d) : "l"(a), "l"(b));
}
__device__ __forceinline__ void unpack2(ull v, float &x, float &y) {
    asm("mov.b64 {%0, %1}, %2;" : "=f"(x), "=f"(y) : "l"(v));
}

// ---------------------------------------------------------------------------
// XLA f32 tanh: Eigen rational poly, FMA-contracted (matches XLA:CPU emission)
// ---------------------------------------------------------------------------
__device__ __forceinline__ float tanh_xla(float x) {
    const float kClamp = 7.90531110763549805f;
    float xc = fminf(fmaxf(x, -kClamp), kClamp);

    const float a1  = 4.89352455891786e-03f;
    const float a3  = 6.37261928875436e-04f;
    const float a5  = 1.48572235717979e-05f;
    const float a7  = 5.12229709037114e-08f;
    const float a9  = -8.60467152213735e-11f;
    const float a11 = 2.00018790482477e-13f;
    const float a13 = -2.76076847742355e-16f;
    const float b0  = 4.89352518554385e-03f;
    const float b2  = 2.26843463243900e-03f;
    const float b4  = 1.18534705686654e-04f;
    const float b6  = 1.19825839466702e-06f;

    float x2 = __fmul_rn(xc, xc);

    float p = a13;
    p = fmaf(x2, p, a11);
    p = fmaf(x2, p, a9);
    p = fmaf(x2, p, a7);
    p = fmaf(x2, p, a5);
    p = fmaf(x2, p, a3);
    p = fmaf(x2, p, a1);
    float num = __fmul_rn(xc, p);

    float q = b6;
    q = fmaf(x2, q, b4);
    q = fmaf(x2, q, b2);
    q = fmaf(x2, q, b0);

    float ratio = __fdiv_rn(num, q);
    return (fabsf(x) < 0.0004f) ? x : ratio;
}

// XLA logistic expander: 0.5 + 0.5 * tanh(0.5 * x), final add contracted.
__device__ __forceinline__ float sigmoid_xla(float x) {
    float t = tanh_xla(__fmul_rn(0.5f, x));
    return fmaf(0.5f, t, 0.5f);
}

// ---------------------------------------------------------------------------
// gi GEMM: C[M,768] = A[M,K] * W[768,K]^T, FFMA2 over m-pairs.
// Each output remains ONE serial ascending-k FMA chain from zero.
// BM=64, BN=64, BK=16, 128 threads, per-thread 4 m-pairs x 4 n.
// ---------------------------------------------------------------------------
template<int K>
__global__ __launch_bounds__(128) void sgemm_nt2(
    const float* __restrict__ A, const float* __restrict__ W, float* __restrict__ C)
{
    __shared__ alignas(8) float As[16][66];
    __shared__ float Ws[16][66];

    const int tid = threadIdx.x;
    const int tn  = tid & 15;
    const int tm  = tid >> 4;
    const size_t m0 = (size_t)blockIdx.x * 64;
    const int    n0 = blockIdx.y * 64;

    const int lk = tid & 15;
    const int lm = tid >> 4;

    ull acc[4][4];   // [m-pair][n]
#pragma unroll
    for (int p = 0; p < 4; p++)
#pragma unroll
        for (int j = 0; j < 4; j++) acc[p][j] = 0ULL;

#pragma unroll 1
    for (int k0 = 0; k0 < K; k0 += 16) {
#pragma unroll
        for (int it = 0; it < 8; it++) {
            int m = lm + it * 8;
            As[lk][m] = A[(m0 + m) * K + (k0 + lk)];
            Ws[lk][m] = W[(size_t)(n0 + m) * K + (k0 + lk)];
        }
        __syncthreads();
#pragma unroll
        for (int kk = 0; kk < 16; kk++) {
            ull a[4];
#pragma unroll
            for (int p = 0; p < 4; p++)
                a[p] = *(const ull*)&As[kk][tm * 8 + 2 * p];
#pragma unroll
            for (int j = 0; j < 4; j++) {
                ull w2 = dup2(Ws[kk][tn * 4 + j]);
#pragma unroll
                for (int p = 0; p < 4; p++)
                    ffma2(acc[p][j], a[p], w2);
            }
        }
        __syncthreads();
    }

#pragma unroll
    for (int p = 0; p < 4; p++) {
        size_t r0 = m0 + tm * 8 + 2 * p;
#pragma unroll
        for (int j = 0; j < 4; j++) {
            float lo, hi;
            unpack2(acc[p][j], lo, hi);
            C[r0 * G3 + (n0 + tn * 4 + j)]       = lo;
            C[(r0 + 1) * G3 + (n0 + tn * 4 + j)] = hi;
        }
    }
}

// ---------------------------------------------------------------------------
// Fused GRU step: per block [64m x 16h] tile, computes all 3 gates
// (48 rows of Whh), applies exact XLA combine, writes sign to h_out.
// grid (32, 16), 128 threads. Double-buffered h removes cross-block WAR.
// ---------------------------------------------------------------------------
__global__ __launch_bounds__(128) void gru_step(
    const float* __restrict__ gi_all,  // [B, T, 768]
    const float* __restrict__ Whh,     // [768, 256]
    const float* __restrict__ b_ih, const float* __restrict__ b_hh,
    const float* __restrict__ h_in,    // [B, 256]
    float* __restrict__ h_out,         // [B, 256]
    int t, float* __restrict__ out, int is_last)
{
    __shared__ alignas(8) float As[32][66];  // h tile [kk][m]
    __shared__ float Ws[32][49];             // W tile [kk][3*16 gate-cols]

    const int tid = threadIdx.x;
    const int tn  = tid & 15;   // h column
    const int tm  = tid >> 4;   // 0..7 -> 8 m rows (4 pairs)
    const int m0  = blockIdx.x * 64;
    const int h0  = blockIdx.y * 16;

    ull acc[3][4];  // [gate][m-pair]
#pragma unroll
    for (int g = 0; g < 3; g++)
#pragma unroll
        for (int p = 0; p < 4; p++) acc[g][p] = 0ULL;

#pragma unroll 1
    for (int k0 = 0; k0 < H_DIM; k0 += 32) {
        // fill h tile: 64 x 32 = 2048 elems, 16 per thread (coalesced over k)
#pragma unroll
        for (int i = 0; i < 16; i++) {
            int e = tid + i * 128;
            int mm = e >> 5, kk = e & 31;
            As[kk][mm] = h_in[(size_t)(m0 + mm) * H_DIM + k0 + kk];
        }
        // fill W tile: 48 x 32 = 1536 elems, 12 per thread (coalesced over k)
#pragma unroll
        for (int i = 0; i < 12; i++) {
            int e = tid + i * 128;
            int col = e >> 5, kk = e & 31;
            int row = (col >> 4) * H_DIM + h0 + (col & 15);
            Ws[kk][col] = Whh[(size_t)row * H_DIM + k0 + kk];
        }
        __syncthreads();
#pragma unroll
        for (int kk = 0; kk < 32; kk++) {
            ull a[4];
#pragma unroll
            for (int p = 0; p < 4; p++)
                a[p] = *(const ull*)&As[kk][tm * 8 + 2 * p];
#pragma unroll
            for (int g = 0; g < 3; g++) {
                ull w2 = dup2(Ws[kk][g * 16 + tn]);
#pragma unroll
                for (int p = 0; p < 4; p++)
                    ffma2(acc[g][p], a[p], w2);
            }
        }
        __syncthreads();
    }

    // Epilogue: exact XLA combine + sign
    const int hc = h0 + tn;
    const float b_ir = b_ih[hc], b_iz = b_ih[hc + H_DIM], b_in = b_ih[hc + 2 * H_DIM];
    const float b_hr = b_hh[hc], b_hz = b_hh[hc + H_DIM], b_hn = b_hh[hc + 2 * H_DIM];

#pragma unroll
    for (int p = 0; p < 4; p++) {
        float gr[2], gz[2], gn[2];
        unpack2(acc[0][p], gr[0], gr[1]);
        unpack2(acc[1][p], gz[0], gz[1]);
        unpack2(acc[2][p], gn[0], gn[1]);
#pragma unroll
        for (int half = 0; half < 2; half++) {
            int m = m0 + tm * 8 + 2 * p + half;
            const float* gi = gi_all + ((size_t)m * T_DIM + t) * G3;

            float i_r = __fadd_rn(gi[hc],             b_ir);
            float i_z = __fadd_rn(gi[hc +     H_DIM], b_iz);
            float i_n = __fadd_rn(gi[hc + 2 * H_DIM], b_in);
            float h_r = __fadd_rn(gr[half], b_hr);
            float h_z = __fadd_rn(gz[half], b_hz);
            float h_n = __fadd_rn(gn[half], b_hn);

            float r = sigmoid_xla(__fadd_rn(i_r, h_r));
            float z = sigmoid_xla(__fadd_rn(i_z, h_z));
            float n = tanh_xla(fmaf(r, h_n, i_n));

            float hprev = h_in[(size_t)m * H_DIM + hc];
            float one_minus_z = __fsub_rn(1.0f, z);
            float zh   = __fmul_rn(z, hprev);
            float hnew = fmaf(one_minus_z, n, zh);

            float s = (hnew > 0.0f) ? 1.0f : ((hnew < 0.0f) ? -1.0f : 0.0f);

            h_out[(size_t)m * H_DIM + hc] = s;
            if (is_last) out[(size_t)m * H_DIM + hc] = s;
        }
    }
}

extern "C" void kernel_launch(void* const* d_in, const int* in_sizes, int n_in,
                              void* d_out, int out_size)
{
    const float* x   = (const float*)d_in[0];  // [2048, 256, 128]
    const float* Wih = (const float*)d_in[1];  // [768, 128]
    const float* Whh = (const float*)d_in[2];  // [768, 256]
    const float* bih = (const float*)d_in[3];  // [768]
    const float* bhh = (const float*)d_in[4];  // [768]
    float* out = (float*)d_out;                // [2048, 256]

    float *gi_p, *h0_p, *h1_p;
    cudaGetSymbolAddress((void**)&gi_p, g_gi);
    cudaGetSymbolAddress((void**)&h0_p, g_h0);
    cudaGetSymbolAddress((void**)&h1_p, g_h1);

    cudaMemsetAsync(h0_p, 0, sizeof(float) * (size_t)B_DIM * H_DIM);

    // Phase 1: gi = X @ W_ih^T for all timesteps (M = B*T = 524288, K = 128).
    {
        dim3 grid((B_DIM * T_DIM) / 64, G3 / 64);
        sgemm_nt2<IN_DIM><<<grid, 128>>>(x, Wih, gi_p);
    }

    // Phase 2: fused sequential recurrence (double-buffered h).
    {
        dim3 grid(B_DIM / 64, H_DIM / 16);
        float* ha = h0_p;
        float* hb = h1_p;
        for (int t = 0; t < T_DIM; t++) {
            gru_step<<<grid, 128>>>(gi_p, Whh, bih, bhh, ha, hb, t, out,
                                    (t == T_DIM - 1) ? 1 : 0);
            float* tmp = ha; ha = hb; hb = tmp;
        }
    }
}